// round 9
// baseline (speedup 1.0000x reference)
#include <cuda_runtime.h>
#include <cuda_bf16.h>
#include <cstdint>

#define N_NODES  50000
#define SEQ      12
#define CH       128
#define BS       4
#define TM       64           // nodes per tile
#define NTHREADS 256          // warps 0-3: GEMM, warps 4-7: gather
#define AP       136          // bf16 A-tile pitch (elements): ldmatrix conflict-free
#define GP       132          // gate fp32 pitch

typedef unsigned long long ull;
typedef unsigned int       uint32;

// ---- smem: A tile + gate (no overlays; single buffers, WS pipeline) ----
#define SM_A0    0                      // A hi bf16 [64][AP]   17408 B
#define SM_A1    17408                  // A lo                 17408 B
#define SM_GATE  34816                  // fp32 [64][GP]        33792 B
#define SM_TOTAL 68608

// W fragments for n64 warp tiles, coalesced, hi/lo separate so the hi table
// serves two passes per load: uint4 at [((ns2*8+kb)*4+q)*32 + lane]
__device__ uint4 g_wfH[2*8*4*32];       // 32 KB
__device__ uint4 g_wfL[2*8*4*32];       // 32 KB

__device__ __forceinline__ ull fma2(ull a, ull b, ull c){ull d;asm("fma.rn.f32x2 %0,%1,%2,%3;":"=l"(d):"l"(a),"l"(b),"l"(c));return d;}
__device__ __forceinline__ ull mul2(ull a, ull b){ull d;asm("mul.rn.f32x2 %0,%1,%2;":"=l"(d):"l"(a),"l"(b));return d;}
__device__ __forceinline__ ull add2(ull a, ull b){ull d;asm("add.rn.f32x2 %0,%1,%2;":"=l"(d):"l"(a),"l"(b));return d;}
__device__ __forceinline__ ull dup2(float a){ull d;asm("mov.b64 %0,{%1,%1};":"=l"(d):"f"(a));return d;}
__device__ __forceinline__ ull pack2(float lo,float hi){ull d;asm("mov.b64 %0,{%1,%2};":"=l"(d):"f"(lo),"f"(hi));return d;}

__device__ __forceinline__ uint32 smem_u32(const void* p){
    uint32 a; asm("{.reg .u64 t; cvta.to.shared.u64 t,%1; cvt.u32.u64 %0,t;}":"=r"(a):"l"(p)); return a;
}
__device__ __forceinline__ void split2(float x, float y, uint32& hi, uint32& lo){
    __nv_bfloat16 bx = __float2bfloat16_rn(x), by = __float2bfloat16_rn(y);
    float rx = x - __bfloat162float(bx), ry = y - __bfloat162float(by);
    __nv_bfloat162 h; h.x = bx; h.y = by;
    __nv_bfloat162 l; l.x = __float2bfloat16_rn(rx); l.y = __float2bfloat16_rn(ry);
    hi = *reinterpret_cast<uint32*>(&h);
    lo = *reinterpret_cast<uint32*>(&l);
}
__device__ __forceinline__ void ldsm_x4(uint32& a0,uint32& a1,uint32& a2,uint32& a3, uint32 addr){
    asm volatile("ldmatrix.sync.aligned.m8n8.x4.shared.b16 {%0,%1,%2,%3},[%4];"
                 : "=r"(a0),"=r"(a1),"=r"(a2),"=r"(a3) : "r"(addr));
}
__device__ __forceinline__ void hmma(float* c, const uint32* a, const uint32* b){
    asm volatile("mma.sync.aligned.m16n8k16.row.col.f32.bf16.bf16.f32 "
                 "{%0,%1,%2,%3},{%4,%5,%6,%7},{%8,%9},{%0,%1,%2,%3};"
                 : "+f"(c[0]),"+f"(c[1]),"+f"(c[2]),"+f"(c[3])
                 : "r"(a[0]),"r"(a[1]),"r"(a[2]),"r"(a[3]),"r"(b[0]),"r"(b[1]));
}
__device__ __forceinline__ void ldg_cg_v4(const float* p, ull& x, ull& y){
    asm("ld.global.cg.v2.u64 {%0,%1},[%2];" : "=l"(x),"=l"(y) : "l"(p));
}

#define BAR_SYNC(id,cnt)   asm volatile("bar.sync %0,%1;"   :: "r"(id), "r"(cnt) : "memory")
#define BAR_ARRIVE(id,cnt) asm volatile("bar.arrive %0,%1;" :: "r"(id), "r"(cnt) : "memory")
#define MEMBAR_CTA()       asm volatile("membar.cta;" ::: "memory")
// bar 0: "gate ready"    (MMA arrive, gather sync)
// bar 1: "gate consumed" (gather arrive, MMA sync)
// bar 2: MMA-internal A-stage barrier (128 threads)

// ---- build kernel: W fragments (hi/lo) for n64 warp tiles ----
__global__ void build_wfrag_kernel(const float* __restrict__ gate_w)
{
    int slot = blockIdx.x*blockDim.x + threadIdx.x;   // 0..511
    if (slot >= 2*8*32) return;
    int lane = slot & 31;
    int kb   = (slot >> 5) & 7;
    int ns2  = slot >> 8;                              // 0..1
    #pragma unroll
    for (int q = 0; q < 4; q++) {
        uint32 h[2][2], l[2][2];
        #pragma unroll
        for (int j = 0; j < 2; j++) {                  // nb = 2q + j
            int n = ns2*64 + (2*q + j)*8 + (lane >> 2);
            #pragma unroll
            for (int i = 0; i < 2; i++) {
                int k0 = kb*16 + i*8 + (lane & 3)*2;
                split2(gate_w[n*CH + k0], gate_w[n*CH + k0 + 1], h[j][i], l[j][i]);
            }
        }
        int idx = ((ns2*8 + kb)*4 + q)*32 + lane;
        uint4 H; H.x = h[0][0]; H.y = h[0][1]; H.z = h[1][0]; H.w = h[1][1];
        uint4 L; L.x = l[0][0]; L.y = l[0][1]; L.z = l[1][0]; L.w = l[1][1];
        g_wfH[idx] = H;
        g_wfL[idx] = L;
    }
}

__global__ void __launch_bounds__(NTHREADS, 2)
gated_spiral_kernel(const float* __restrict__ x,
                    const int*   __restrict__ indices,
                    const float* __restrict__ weight,
                    const float* __restrict__ gate_b,
                    float*       __restrict__ out)
{
    extern __shared__ char smem[];
    const uint32 sb = smem_u32(smem);
    float* gate_s = (float*)(smem + SM_GATE);

    const int tid  = threadIdx.x;
    const int wid  = tid >> 5;
    const int lane = tid & 31;
    const bool is_mma = (wid < 4);

    const int tiles_per_batch = (N_NODES + TM - 1) / TM;   // 782
    const int total_tiles     = BS * tiles_per_batch;      // 3128

    if (is_mma) {
        // =================== GEMM / producer warps ===================
        const int ms  = wid & 1;          // m-slice (32 rows)
        const int ns2 = wid >> 1;         // n-half  (64 cols)
        const uint32 aoff0 = (uint32)((ms*32      + (lane & 15))*AP + (lane >> 4)*8) * 2;
        const uint32 aoff1 = (uint32)((ms*32 + 16 + (lane & 15))*AP + (lane >> 4)*8) * 2;

        auto stageA = [&](int tt) {
            const int bb  = tt / tiles_per_batch;
            const int vv0 = (tt - bb * tiles_per_batch) * TM;
            const int nv  = min(TM, N_NODES - vv0);
            const float* xs = x + (size_t)bb * (size_t)N_NODES * CH;
            #pragma unroll
            for (int k = 0; k < 16; k++) {             // 64*32 float4 / 128 thr = 16 iters
                int i  = tid + k*128;
                int r  = i >> 5;
                int k4 = (i & 31) << 2;
                const float* p = xs + (size_t)(vv0 + min(r, nv - 1))*CH + k4;
                ull lo, hi2; ldg_cg_v4(p, lo, hi2);
                float2 v01 = *reinterpret_cast<float2*>(&lo);
                float2 v23 = *reinterpret_cast<float2*>(&hi2);
                uint32 h0,l0,h1,l1;
                split2(v01.x, v01.y, h0, l0);
                split2(v23.x, v23.y, h1, l1);
                uint32 o = (uint32)(r*AP + k4) * 2;
                *(ull*)(smem + SM_A0 + o) = ((ull)h1 << 32) | h0;
                *(ull*)(smem + SM_A1 + o) = ((ull)l1 << 32) | l0;
            }
        };

        int t = blockIdx.x;
        if (t < total_tiles) stageA(t);
        BAR_SYNC(2, 128);                              // A(first) visible to MMA warps

        for (; t < total_tiles; t += gridDim.x) {
            // ---- GEMM(t): runs concurrent with gather(t-1) ----
            float acc[2][8][4];
            #pragma unroll
            for (int mi = 0; mi < 2; mi++)
                #pragma unroll
                for (int nb = 0; nb < 8; nb++)
                    #pragma unroll
                    for (int j = 0; j < 4; j++) acc[mi][nb][j] = 0.f;

            #pragma unroll
            for (int kb = 0; kb < 8; kb++) {
                const uint32 ko = kb*32;
                uint32 ah[2][4], al[2][4], bw[16];
                ldsm_x4(ah[0][0],ah[0][1],ah[0][2],ah[0][3], sb + SM_A0 + aoff0 + ko);
                ldsm_x4(ah[1][0],ah[1][1],ah[1][2],ah[1][3], sb + SM_A0 + aoff1 + ko);
                ldsm_x4(al[0][0],al[0][1],al[0][2],al[0][3], sb + SM_A1 + aoff0 + ko);
                ldsm_x4(al[1][0],al[1][1],al[1][2],al[1][3], sb + SM_A1 + aoff1 + ko);
                const int wbase = ((ns2*8 + kb)*4)*32 + lane;
                #pragma unroll
                for (int q = 0; q < 4; q++)
                    *reinterpret_cast<uint4*>(&bw[q*4]) = g_wfH[wbase + q*32];
                #pragma unroll
                for (int mi = 0; mi < 2; mi++)
                    #pragma unroll
                    for (int nb = 0; nb < 8; nb++)
                        hmma(acc[mi][nb], ah[mi], &bw[nb*2]);   // hi*hi
                #pragma unroll
                for (int mi = 0; mi < 2; mi++)
                    #pragma unroll
                    for (int nb = 0; nb < 8; nb++)
                        hmma(acc[mi][nb], al[mi], &bw[nb*2]);   // lo*hi  (al dead after)
                #pragma unroll
                for (int q = 0; q < 4; q++)
                    *reinterpret_cast<uint4*>(&bw[q*4]) = g_wfL[wbase + q*32];
                #pragma unroll
                for (int mi = 0; mi < 2; mi++)
                    #pragma unroll
                    for (int nb = 0; nb < 8; nb++)
                        hmma(acc[mi][nb], ah[mi], &bw[nb*2]);   // hi*lo
            }

            BAR_SYNC(1, 256);                          // wait: gather(t-1) done with gate

            // ---- Epilogue: acc -> gate_s ----
            #pragma unroll
            for (int mi = 0; mi < 2; mi++) {
                int r0 = ms*32 + mi*16 + (lane >> 2);
                #pragma unroll
                for (int nb = 0; nb < 8; nb++) {
                    int c = ns2*64 + nb*8 + (lane & 3)*2;
                    *reinterpret_cast<ull*>(gate_s + r0*GP + c)     = pack2(acc[mi][nb][0], acc[mi][nb][1]);
                    *reinterpret_cast<ull*>(gate_s + (r0+8)*GP + c) = pack2(acc[mi][nb][2], acc[mi][nb][3]);
                }
            }
            MEMBAR_CTA();
            BAR_ARRIVE(0, 256);                        // gate ready -> gather(t) may go

            // ---- Stage A(t+grid) while gather(t) runs ----
            const int nxt = t + gridDim.x;
            if (nxt < total_tiles) stageA(nxt);
            BAR_SYNC(2, 128);                          // A staged + visible to MMA warps
        }
    } else {
        // =================== gather / consumer warps ===================
        const int gw = wid - 4;                        // 0..3 -> 16 nodes each
        const ull bias0 = *reinterpret_cast<const ull*>(gate_b + lane*4);
        const ull bias1 = *reinterpret_cast<const ull*>(gate_b + lane*4 + 2);

        BAR_ARRIVE(1, 256);                            // prime "gate consumed"

        for (int t = blockIdx.x; t < total_tiles; t += gridDim.x) {
            const int b      = t / tiles_per_batch;
            const int v0     = (t - b * tiles_per_batch) * TM;
            const int nvalid = min(TM, N_NODES - v0);
            const float* __restrict__ xb = x + (size_t)b * (size_t)N_NODES * CH;

            BAR_SYNC(0, 256);                          // wait gate(t) ready

            #pragma unroll 1
            for (int nn = 0; nn < 16; nn++) {
                const int node = gw*16 + nn;
                if (node < nvalid) {
                    const int base = (v0 + node)*SEQ;
                    int4   ia = *reinterpret_cast<const int4*>(indices + base);
                    int4   ib = *reinterpret_cast<const int4*>(indices + base + 4);
                    int4   ic = *reinterpret_cast<const int4*>(indices + base + 8);
                    float4 wa = *reinterpret_cast<const float4*>(weight + base);
                    float4 wb = *reinterpret_cast<const float4*>(weight + base + 4);
                    float4 wc = *reinterpret_cast<const float4*>(weight + base + 8);
                    ull a0 = 0, a1 = 0;
                    #define GACC(II, WW) { \
                        const float* src = xb + (size_t)(uint32)(II)*CH + lane*4; \
                        ull p0, p1; ldg_cg_v4(src, p0, p1); \
                        ull W = dup2(WW); \
                        a0 = fma2(W, p0, a0); a1 = fma2(W, p1, a1); }
                    GACC(ia.x, wa.x) GACC(ia.y, wa.y) GACC(ia.z, wa.z) GACC(ia.w, wa.w)
                    GACC(ib.x, wb.x) GACC(ib.y, wb.y) GACC(ib.z, wb.z) GACC(ib.w, wb.w)
                    GACC(ic.x, wc.x) GACC(ic.y, wc.y) GACC(ic.z, wc.z) GACC(ic.w, wc.w)
                    #undef GACC
                    ulonglong2 gp = *reinterpret_cast<const ulonglong2*>(gate_s + node*GP + lane*4);
                    ull o0 = mul2(a0, add2(gp.x, bias0));
                    ull o1 = mul2(a1, add2(gp.y, bias1));
                    float* op = out + ((size_t)b*N_NODES + (size_t)(v0 + node))*CH + lane*4;
                    asm volatile("st.global.cs.v2.b64 [%0], {%1,%2};" :: "l"(op), "l"(o0), "l"(o1) : "memory");
                }
            }
            MEMBAR_CTA();
            BAR_ARRIVE(1, 256);                        // gate consumed -> next epilogue may write
        }
    }
}

extern "C" void kernel_launch(void* const* d_in, const int* in_sizes, int n_in,
                              void* d_out, int out_size)
{
    (void)in_sizes; (void)n_in; (void)out_size;
    const float* x       = (const float*)d_in[0];
    const int*   indices = (const int*)  d_in[1];
    const float* weight  = (const float*)d_in[2];
    const float* gate_w  = (const float*)d_in[3];
    const float* gate_b  = (const float*)d_in[4];
    float*       out     = (float*)d_out;

    build_wfrag_kernel<<<2, 256>>>(gate_w);

    cudaFuncSetAttribute(gated_spiral_kernel,
                         cudaFuncAttributeMaxDynamicSharedMemorySize, SM_TOTAL);

    int sm_count = 148;
    cudaDeviceGetAttribute(&sm_count, cudaDevAttrMultiProcessorCount, 0);

    gated_spiral_kernel<<<2*sm_count, NTHREADS, SM_TOTAL>>>(
        x, indices, weight, gate_b, out);
}

// round 10
// speedup vs baseline: 1.1581x; 1.1581x over previous
#include <cuda_runtime.h>
#include <cuda_bf16.h>
#include <cstdint>

#define N_NODES  50000
#define SEQ      12
#define CH       128
#define BS       4
#define TM       64           // nodes per tile
#define NTHREADS 256
#define AP       136          // bf16 A-tile pitch (elements)
#define GP       132          // gate fp32 pitch

typedef unsigned long long ull;
typedef unsigned int       uint32;

// ---- smem: A tile, overlaid by gate after MMA ----
#define SM_A0    0                      // A hi bf16 [64][AP]   17408 B
#define SM_A1    17408                  // A lo                 17408 B
#define SM_GATE  0                      // fp32 [64][GP] 33792 B, overlays A0+A1
#define SM_TOTAL 34816

// W fragments, coalesced: uint4 (h0,h1,l0,l1) at [((ns*8+kb)*4+nb)*32 + lane]
__device__ uint4 g_wfrag[4*8*4*32];     // 64 KB

__device__ __forceinline__ ull fma2(ull a, ull b, ull c){ull d;asm("fma.rn.f32x2 %0,%1,%2,%3;":"=l"(d):"l"(a),"l"(b),"l"(c));return d;}
__device__ __forceinline__ ull mul2(ull a, ull b){ull d;asm("mul.rn.f32x2 %0,%1,%2;":"=l"(d):"l"(a),"l"(b));return d;}
__device__ __forceinline__ ull add2(ull a, ull b){ull d;asm("add.rn.f32x2 %0,%1,%2;":"=l"(d):"l"(a),"l"(b));return d;}
__device__ __forceinline__ ull dup2(float a){ull d;asm("mov.b64 %0,{%1,%1};":"=l"(d):"f"(a));return d;}
__device__ __forceinline__ ull pack2(float lo,float hi){ull d;asm("mov.b64 %0,{%1,%2};":"=l"(d):"f"(lo),"f"(hi));return d;}

__device__ __forceinline__ uint32 smem_u32(const void* p){
    uint32 a; asm("{.reg .u64 t; cvta.to.shared.u64 t,%1; cvt.u32.u64 %0,t;}":"=r"(a):"l"(p)); return a;
}
__device__ __forceinline__ void split2(float x, float y, uint32& hi, uint32& lo){
    __nv_bfloat16 bx = __float2bfloat16_rn(x), by = __float2bfloat16_rn(y);
    float rx = x - __bfloat162float(bx), ry = y - __bfloat162float(by);
    __nv_bfloat162 h; h.x = bx; h.y = by;
    __nv_bfloat162 l; l.x = __float2bfloat16_rn(rx); l.y = __float2bfloat16_rn(ry);
    hi = *reinterpret_cast<uint32*>(&h);
    lo = *reinterpret_cast<uint32*>(&l);
}
__device__ __forceinline__ void ldsm_x4(uint32& a0,uint32& a1,uint32& a2,uint32& a3, uint32 addr){
    asm volatile("ldmatrix.sync.aligned.m8n8.x4.shared.b16 {%0,%1,%2,%3},[%4];"
                 : "=r"(a0),"=r"(a1),"=r"(a2),"=r"(a3) : "r"(addr));
}
__device__ __forceinline__ void hmma(float* c, const uint32* a, const uint32* b){
    asm volatile("mma.sync.aligned.m16n8k16.row.col.f32.bf16.bf16.f32 "
                 "{%0,%1,%2,%3},{%4,%5,%6,%7},{%8,%9},{%0,%1,%2,%3};"
                 : "+f"(c[0]),"+f"(c[1]),"+f"(c[2]),"+f"(c[3])
                 : "r"(a[0]),"r"(a[1]),"r"(a[2]),"r"(a[3]),"r"(b[0]),"r"(b[1]));
}
__device__ __forceinline__ void ldg_cg_v4(const float* p, ull& x, ull& y){
    asm("ld.global.cg.v2.u64 {%0,%1},[%2];" : "=l"(x),"=l"(y) : "l"(p));
}

// ---- build kernel: HMMA B fragments, coalesced (h0,h1,l0,l1) ----
__global__ void build_wfrag_kernel(const float* __restrict__ gate_w)
{
    int slot = blockIdx.x*blockDim.x + threadIdx.x;   // 0..1023
    if (slot >= 4*8*32) return;
    int lane = slot & 31;
    int kb   = (slot >> 5) & 7;
    int ns   = slot >> 8;
    #pragma unroll
    for (int nb = 0; nb < 4; nb++) {
        int n = ns*32 + nb*8 + (lane >> 2);
        uint32 h[2], l[2];
        #pragma unroll
        for (int i = 0; i < 2; i++) {
            int k0 = kb*16 + i*8 + (lane & 3)*2;
            split2(gate_w[n*CH + k0], gate_w[n*CH + k0 + 1], h[i], l[i]);
        }
        uint4 v; v.x = h[0]; v.y = h[1]; v.z = l[0]; v.w = l[1];
        g_wfrag[(((ns << 3) + kb)*4 + nb)*32 + lane] = v;
    }
}

__global__ void __launch_bounds__(NTHREADS, 2)
gated_spiral_kernel(const float* __restrict__ x,
                    const int*   __restrict__ indices,
                    const float* __restrict__ weight,
                    const float* __restrict__ gate_b,
                    float*       __restrict__ out)
{
    extern __shared__ char smem[];
    const uint32 sb = smem_u32(smem);
    float* gate_s = (float*)(smem + SM_GATE);

    const int tid  = threadIdx.x;
    const int wid  = tid >> 5;
    const int lane = tid & 31;

    const ull bias0 = *reinterpret_cast<const ull*>(gate_b + lane*4);
    const ull bias1 = *reinterpret_cast<const ull*>(gate_b + lane*4 + 2);

    // MMA role: 8 warps = 2m x 4n grid; warp tile m32 x n32
    const int ms = wid & 1;
    const int ns = wid >> 1;
    const uint32 aoff0 = (uint32)((ms*32      + (lane & 15))*AP + (lane >> 4)*8) * 2;
    const uint32 aoff1 = (uint32)((ms*32 + 16 + (lane & 15))*AP + (lane >> 4)*8) * 2;

    const int tiles_per_batch = (N_NODES + TM - 1) / TM;   // 782
    const int total_tiles     = BS * tiles_per_batch;      // 3128

    // ---- stage A tile only (idx/wt now read directly from gmem in gather) ----
    auto stage = [&](int tt) {
        const int bb  = tt / tiles_per_batch;
        const int vv0 = (tt - bb * tiles_per_batch) * TM;
        const int nv  = min(TM, N_NODES - vv0);
        const float* xs = x + (size_t)bb * (size_t)N_NODES * CH;
        #pragma unroll
        for (int k = 0; k < 8; k++) {                  // 64*32 float4 / 256 thr
            int i  = tid + k*NTHREADS;
            int r  = i >> 5;
            int k4 = (i & 31) << 2;
            const float* p = xs + (size_t)(vv0 + min(r, nv - 1))*CH + k4;
            ull lo, hi2; ldg_cg_v4(p, lo, hi2);
            float2 v01 = *reinterpret_cast<float2*>(&lo);
            float2 v23 = *reinterpret_cast<float2*>(&hi2);
            uint32 h0,l0,h1,l1;
            split2(v01.x, v01.y, h0, l0);
            split2(v23.x, v23.y, h1, l1);
            uint32 o = (uint32)(r*AP + k4) * 2;
            *(ull*)(smem + SM_A0 + o) = ((ull)h1 << 32) | h0;
            *(ull*)(smem + SM_A1 + o) = ((ull)l1 << 32) | l0;
        }
    };

    int t = blockIdx.x;
    if (t < total_tiles) stage(t);

    for (; t < total_tiles; t += gridDim.x) {
        const int b      = t / tiles_per_batch;
        const int v0     = (t - b * tiles_per_batch) * TM;
        const int nvalid = min(TM, N_NODES - v0);
        const float* __restrict__ xb = x + (size_t)b * (size_t)N_NODES * CH;

        __syncthreads();   // A(t) visible

        // ---- HMMA: gate = A x W^T ----
        float acc[2][4][4];
        #pragma unroll
        for (int mi = 0; mi < 2; mi++)
            #pragma unroll
            for (int nb = 0; nb < 4; nb++)
                #pragma unroll
                for (int j = 0; j < 4; j++) acc[mi][nb][j] = 0.f;

        #pragma unroll
        for (int kb = 0; kb < 8; kb++) {
            const uint32 ko = kb*32;
            uint32 ah[2][4], al[2][4], bf[16];
            ldsm_x4(ah[0][0],ah[0][1],ah[0][2],ah[0][3], sb + SM_A0 + aoff0 + ko);
            ldsm_x4(ah[1][0],ah[1][1],ah[1][2],ah[1][3], sb + SM_A0 + aoff1 + ko);
            ldsm_x4(al[0][0],al[0][1],al[0][2],al[0][3], sb + SM_A1 + aoff0 + ko);
            ldsm_x4(al[1][0],al[1][1],al[1][2],al[1][3], sb + SM_A1 + aoff1 + ko);
            const uint4* wp = g_wfrag + (((ns << 3) + kb) << 2)*32 + lane;
            #pragma unroll
            for (int q = 0; q < 4; q++)
                *reinterpret_cast<uint4*>(&bf[q*4]) = wp[q*32];
            #pragma unroll
            for (int mi = 0; mi < 2; mi++)
                #pragma unroll
                for (int nb = 0; nb < 4; nb++) {
                    hmma(acc[mi][nb], ah[mi], &bf[nb*4]);       // hi*hi
                    hmma(acc[mi][nb], ah[mi], &bf[nb*4 + 2]);   // hi*lo
                    hmma(acc[mi][nb], al[mi], &bf[nb*4]);       // lo*hi
                }
        }
        __syncthreads();   // all ldsm retired before gate overlays A

        // ---- Epilogue: acc -> gate_s ----
        #pragma unroll
        for (int mi = 0; mi < 2; mi++) {
            int r0 = ms*32 + mi*16 + (lane >> 2);
            #pragma unroll
            for (int nb = 0; nb < 4; nb++) {
                int c = ns*32 + nb*8 + (lane & 3)*2;
                *reinterpret_cast<ull*>(gate_s + r0*GP + c)     = pack2(acc[mi][nb][0], acc[mi][nb][1]);
                *reinterpret_cast<ull*>(gate_s + (r0+8)*GP + c) = pack2(acc[mi][nb][2], acc[mi][nb][3]);
            }
        }
        __syncthreads();   // gate visible

        // ---- Gather: warp-per-row, 2 nodes in flight (24 outstanding LDG.128) ----
        if (nvalid == TM) {
            #pragma unroll 1
            for (int nn = 0; nn < 8; nn += 2) {
                const int n0   = wid*8 + nn;
                const int base = (v0 + n0)*SEQ;
                int4   ia0 = *reinterpret_cast<const int4*>(indices + base);
                int4   ib0 = *reinterpret_cast<const int4*>(indices + base + 4);
                int4   ic0 = *reinterpret_cast<const int4*>(indices + base + 8);
                int4   ia1 = *reinterpret_cast<const int4*>(indices + base + 12);
                int4   ib1 = *reinterpret_cast<const int4*>(indices + base + 16);
                int4   ic1 = *reinterpret_cast<const int4*>(indices + base + 20);
                float4 wa0 = *reinterpret_cast<const float4*>(weight + base);
                float4 wb0 = *reinterpret_cast<const float4*>(weight + base + 4);
                float4 wc0 = *reinterpret_cast<const float4*>(weight + base + 8);
                float4 wa1 = *reinterpret_cast<const float4*>(weight + base + 12);
                float4 wb1 = *reinterpret_cast<const float4*>(weight + base + 16);
                float4 wc1 = *reinterpret_cast<const float4*>(weight + base + 20);
                ull a00=0,a01=0,a10=0,a11=0;
                #define G2(I0,W0,I1,W1) { \
                    const float* s0p = xb + (size_t)(uint32)(I0)*CH + lane*4; \
                    const float* s1p = xb + (size_t)(uint32)(I1)*CH + lane*4; \
                    ull p0,p1,q0,q1; ldg_cg_v4(s0p,p0,p1); ldg_cg_v4(s1p,q0,q1); \
                    ull W0d = dup2(W0), W1d = dup2(W1); \
                    a00 = fma2(W0d,p0,a00); a01 = fma2(W0d,p1,a01); \
                    a10 = fma2(W1d,q0,a10); a11 = fma2(W1d,q1,a11); }
                G2(ia0.x,wa0.x, ia1.x,wa1.x) G2(ia0.y,wa0.y, ia1.y,wa1.y)
                G2(ia0.z,wa0.z, ia1.z,wa1.z) G2(ia0.w,wa0.w, ia1.w,wa1.w)
                G2(ib0.x,wb0.x, ib1.x,wb1.x) G2(ib0.y,wb0.y, ib1.y,wb1.y)
                G2(ib0.z,wb0.z, ib1.z,wb1.z) G2(ib0.w,wb0.w, ib1.w,wb1.w)
                G2(ic0.x,wc0.x, ic1.x,wc1.x) G2(ic0.y,wc0.y, ic1.y,wc1.y)
                G2(ic0.z,wc0.z, ic1.z,wc1.z) G2(ic0.w,wc0.w, ic1.w,wc1.w)
                #undef G2
                ulonglong2 g0 = *reinterpret_cast<const ulonglong2*>(gate_s + n0*GP + lane*4);
                ulonglong2 g1 = *reinterpret_cast<const ulonglong2*>(gate_s + (n0+1)*GP + lane*4);
                ull o00 = mul2(a00, add2(g0.x, bias0));
                ull o01 = mul2(a01, add2(g0.y, bias1));
                ull o10 = mul2(a10, add2(g1.x, bias0));
                ull o11 = mul2(a11, add2(g1.y, bias1));
                float* op = out + ((size_t)b*N_NODES + (size_t)(v0 + n0))*CH + lane*4;
                asm volatile("st.global.cs.v2.b64 [%0], {%1,%2};" :: "l"(op),      "l"(o00), "l"(o01) : "memory");
                asm volatile("st.global.cs.v2.b64 [%0], {%1,%2};" :: "l"(op + CH), "l"(o10), "l"(o11) : "memory");
            }
        } else {
            // tail tile: guarded scalar path
            #pragma unroll 1
            for (int nn = 0; nn < 8; nn++) {
                const int node = wid*8 + nn;
                if (node >= nvalid) break;
                const int base = (v0 + node)*SEQ;
                ull a0 = 0, a1 = 0;
                #pragma unroll
                for (int s = 0; s < SEQ; s++) {
                    int   u  = indices[base + s];
                    float wv = weight [base + s];
                    const float* src = xb + (size_t)(uint32)u*CH + lane*4;
                    ull p0, p1; ldg_cg_v4(src, p0, p1);
                    ull W = dup2(wv);
                    a0 = fma2(W, p0, a0);
                    a1 = fma2(W, p1, a1);
                }
                ulonglong2 gp = *reinterpret_cast<const ulonglong2*>(gate_s + node*GP + lane*4);
                ull o0 = mul2(a0, add2(gp.x, bias0));
                ull o1 = mul2(a1, add2(gp.y, bias1));
                float* op = out + ((size_t)b*N_NODES + (size_t)(v0 + node))*CH + lane*4;
                asm volatile("st.global.cs.v2.b64 [%0], {%1,%2};" :: "l"(op), "l"(o0), "l"(o1) : "memory");
            }
        }

        __syncthreads();   // gather done reading gate

        // ---- Stage next tile (overwrites A/gate smem) ----
        const int nxt = t + gridDim.x;
        if (nxt < total_tiles) stage(nxt);
    }
}

extern "C" void kernel_launch(void* const* d_in, const int* in_sizes, int n_in,
                              void* d_out, int out_size)
{
    (void)in_sizes; (void)n_in; (void)out_size;
    const float* x       = (const float*)d_in[0];
    const int*   indices = (const int*)  d_in[1];
    const float* weight  = (const float*)d_in[2];
    const float* gate_w  = (const float*)d_in[3];
    const float* gate_b  = (const float*)d_in[4];
    float*       out     = (float*)d_out;

    build_wfrag_kernel<<<4, 256>>>(gate_w);

    cudaFuncSetAttribute(gated_spiral_kernel,
                         cudaFuncAttributeMaxDynamicSharedMemorySize, SM_TOTAL);

    int sm_count = 148;
    cudaDeviceGetAttribute(&sm_count, cudaDevAttrMultiProcessorCount, 0);

    gated_spiral_kernel<<<2*sm_count, NTHREADS, SM_TOTAL>>>(
        x, indices, weight, gate_b, out);
}

// round 11
// speedup vs baseline: 1.1633x; 1.0045x over previous
#include <cuda_runtime.h>
#include <cuda_bf16.h>
#include <cstdint>

#define N_NODES  50000
#define SEQ      12
#define CH       128
#define BS       4
#define TM       64           // nodes per tile
#define NTHREADS 256
#define AP       136          // bf16 A-tile pitch (elements)
#define GP       132          // gate fp32 pitch

typedef unsigned long long ull;
typedef unsigned int       uint32;

// ---- smem: A tile, overlaid by gate after MMA ----
#define SM_A0    0                      // A hi bf16 [64][AP]   17408 B
#define SM_A1    17408                  // A lo                 17408 B
#define SM_GATE  0                      // fp32 [64][GP] 33792 B, overlays A0+A1
#define SM_TOTAL 34816

// W fragments, coalesced: uint4 (h0,h1,l0,l1) at [((ns*8+kb)*4+nb)*32 + lane]
__device__ uint4 g_wfrag[4*8*4*32];     // 64 KB

__device__ __forceinline__ ull fma2(ull a, ull b, ull c){ull d;asm("fma.rn.f32x2 %0,%1,%2,%3;":"=l"(d):"l"(a),"l"(b),"l"(c));return d;}
__device__ __forceinline__ ull mul2(ull a, ull b){ull d;asm("mul.rn.f32x2 %0,%1,%2;":"=l"(d):"l"(a),"l"(b));return d;}
__device__ __forceinline__ ull add2(ull a, ull b){ull d;asm("add.rn.f32x2 %0,%1,%2;":"=l"(d):"l"(a),"l"(b));return d;}
__device__ __forceinline__ ull dup2(float a){ull d;asm("mov.b64 %0,{%1,%1};":"=l"(d):"f"(a));return d;}
__device__ __forceinline__ ull pack2(float lo,float hi){ull d;asm("mov.b64 %0,{%1,%2};":"=l"(d):"f"(lo),"f"(hi));return d;}

__device__ __forceinline__ uint32 smem_u32(const void* p){
    uint32 a; asm("{.reg .u64 t; cvta.to.shared.u64 t,%1; cvt.u32.u64 %0,t;}":"=r"(a):"l"(p)); return a;
}
__device__ __forceinline__ void split2(float x, float y, uint32& hi, uint32& lo){
    __nv_bfloat16 bx = __float2bfloat16_rn(x), by = __float2bfloat16_rn(y);
    float rx = x - __bfloat162float(bx), ry = y - __bfloat162float(by);
    __nv_bfloat162 h; h.x = bx; h.y = by;
    __nv_bfloat162 l; l.x = __float2bfloat16_rn(rx); l.y = __float2bfloat16_rn(ry);
    hi = *reinterpret_cast<uint32*>(&h);
    lo = *reinterpret_cast<uint32*>(&l);
}
__device__ __forceinline__ void ldsm_x4(uint32& a0,uint32& a1,uint32& a2,uint32& a3, uint32 addr){
    asm volatile("ldmatrix.sync.aligned.m8n8.x4.shared.b16 {%0,%1,%2,%3},[%4];"
                 : "=r"(a0),"=r"(a1),"=r"(a2),"=r"(a3) : "r"(addr));
}
__device__ __forceinline__ void hmma2(float* c, const uint32* a, uint32 b0, uint32 b1){
    asm volatile("mma.sync.aligned.m16n8k16.row.col.f32.bf16.bf16.f32 "
                 "{%0,%1,%2,%3},{%4,%5,%6,%7},{%8,%9},{%0,%1,%2,%3};"
                 : "+f"(c[0]),"+f"(c[1]),"+f"(c[2]),"+f"(c[3])
                 : "r"(a[0]),"r"(a[1]),"r"(a[2]),"r"(a[3]),"r"(b0),"r"(b1));
}
__device__ __forceinline__ void ldg_cg_v4(const float* p, ull& x, ull& y){
    asm("ld.global.cg.v2.u64 {%0,%1},[%2];" : "=l"(x),"=l"(y) : "l"(p));
}

// ---- build kernel: HMMA B fragments, coalesced (h0,h1,l0,l1) ----
__global__ void build_wfrag_kernel(const float* __restrict__ gate_w)
{
    int slot = blockIdx.x*blockDim.x + threadIdx.x;   // 0..1023
    if (slot >= 4*8*32) return;
    int lane = slot & 31;
    int kb   = (slot >> 5) & 7;
    int ns   = slot >> 8;
    #pragma unroll
    for (int nb = 0; nb < 4; nb++) {
        int n = ns*32 + nb*8 + (lane >> 2);
        uint32 h[2], l[2];
        #pragma unroll
        for (int i = 0; i < 2; i++) {
            int k0 = kb*16 + i*8 + (lane & 3)*2;
            split2(gate_w[n*CH + k0], gate_w[n*CH + k0 + 1], h[i], l[i]);
        }
        uint4 v; v.x = h[0]; v.y = h[1]; v.z = l[0]; v.w = l[1];
        g_wfrag[(((ns << 3) + kb)*4 + nb)*32 + lane] = v;
    }
}

__global__ void __launch_bounds__(NTHREADS, 3)
gated_spiral_kernel(const float* __restrict__ x,
                    const int*   __restrict__ indices,
                    const float* __restrict__ weight,
                    const float* __restrict__ gate_b,
                    float*       __restrict__ out)
{
    extern __shared__ char smem[];
    const uint32 sb = smem_u32(smem);
    float* gate_s = (float*)(smem + SM_GATE);

    const int tid  = threadIdx.x;
    const int wid  = tid >> 5;
    const int lane = tid & 31;

    const ull bias0 = *reinterpret_cast<const ull*>(gate_b + lane*4);
    const ull bias1 = *reinterpret_cast<const ull*>(gate_b + lane*4 + 2);

    // MMA role: 8 warps = 2m x 4n grid; warp tile m32 x n32
    const int ms = wid & 1;
    const int ns = wid >> 1;
    const uint32 aoff0 = (uint32)((ms*32      + (lane & 15))*AP + (lane >> 4)*8) * 2;
    const uint32 aoff1 = (uint32)((ms*32 + 16 + (lane & 15))*AP + (lane >> 4)*8) * 2;

    const int tiles_per_batch = (N_NODES + TM - 1) / TM;   // 782
    const int total_tiles     = BS * tiles_per_batch;      // 3128

    // ---- stage A tile (idx/wt read directly from gmem in gather) ----
    auto stage = [&](int tt) {
        const int bb  = tt / tiles_per_batch;
        const int vv0 = (tt - bb * tiles_per_batch) * TM;
        const int nv  = min(TM, N_NODES - vv0);
        const float* xs = x + (size_t)bb * (size_t)N_NODES * CH;
        #pragma unroll
        for (int k = 0; k < 8; k++) {                  // 64*32 float4 / 256 thr
            int i  = tid + k*NTHREADS;
            int r  = i >> 5;
            int k4 = (i & 31) << 2;
            const float* p = xs + (size_t)(vv0 + min(r, nv - 1))*CH + k4;
            ull lo, hi2; ldg_cg_v4(p, lo, hi2);
            float2 v01 = *reinterpret_cast<float2*>(&lo);
            float2 v23 = *reinterpret_cast<float2*>(&hi2);
            uint32 h0,l0,h1,l1;
            split2(v01.x, v01.y, h0, l0);
            split2(v23.x, v23.y, h1, l1);
            uint32 o = (uint32)(r*AP + k4) * 2;
            *(ull*)(smem + SM_A0 + o) = ((ull)h1 << 32) | h0;
            *(ull*)(smem + SM_A1 + o) = ((ull)l1 << 32) | l0;
        }
    };

    int t = blockIdx.x;
    if (t < total_tiles) stage(t);

    for (; t < total_tiles; t += gridDim.x) {
        const int b      = t / tiles_per_batch;
        const int v0     = (t - b * tiles_per_batch) * TM;
        const int nvalid = min(TM, N_NODES - v0);
        const float* __restrict__ xb = x + (size_t)b * (size_t)N_NODES * CH;

        __syncthreads();   // A(t) visible

        // ---- HMMA: gate = A x W^T; one nb-fragment live at a time (reg budget) ----
        float acc[2][4][4];
        #pragma unroll
        for (int mi = 0; mi < 2; mi++)
            #pragma unroll
            for (int nb = 0; nb < 4; nb++)
                #pragma unroll
                for (int j = 0; j < 4; j++) acc[mi][nb][j] = 0.f;

        #pragma unroll
        for (int kb = 0; kb < 8; kb++) {
            const uint32 ko = kb*32;
            uint32 ah[2][4], al[2][4];
            ldsm_x4(ah[0][0],ah[0][1],ah[0][2],ah[0][3], sb + SM_A0 + aoff0 + ko);
            ldsm_x4(ah[1][0],ah[1][1],ah[1][2],ah[1][3], sb + SM_A0 + aoff1 + ko);
            ldsm_x4(al[0][0],al[0][1],al[0][2],al[0][3], sb + SM_A1 + aoff0 + ko);
            ldsm_x4(al[1][0],al[1][1],al[1][2],al[1][3], sb + SM_A1 + aoff1 + ko);
            const uint4* wp = g_wfrag + (((ns << 3) + kb) << 2)*32 + lane;
            #pragma unroll
            for (int nb = 0; nb < 4; nb++) {
                uint4 w = wp[nb*32];                    // (h0,h1,l0,l1)
                #pragma unroll
                for (int mi = 0; mi < 2; mi++) {
                    hmma2(acc[mi][nb], ah[mi], w.x, w.y);   // hi*hi
                    hmma2(acc[mi][nb], ah[mi], w.z, w.w);   // hi*lo
                    hmma2(acc[mi][nb], al[mi], w.x, w.y);   // lo*hi
                }
            }
        }
        __syncthreads();   // all ldsm retired before gate overlays A

        // ---- Epilogue: acc -> gate_s ----
        #pragma unroll
        for (int mi = 0; mi < 2; mi++) {
            int r0 = ms*32 + mi*16 + (lane >> 2);
            #pragma unroll
            for (int nb = 0; nb < 4; nb++) {
                int c = ns*32 + nb*8 + (lane & 3)*2;
                *reinterpret_cast<ull*>(gate_s + r0*GP + c)     = pack2(acc[mi][nb][0], acc[mi][nb][1]);
                *reinterpret_cast<ull*>(gate_s + (r0+8)*GP + c) = pack2(acc[mi][nb][2], acc[mi][nb][3]);
            }
        }
        __syncthreads();   // gate visible

        // ---- Gather: warp-per-row, 1 node deep (12 outstanding LDG.128) ----
        #pragma unroll 1
        for (int nn = 0; nn < 8; nn++) {
            const int node = wid*8 + nn;
            if (node >= nvalid) break;
            const int base = (v0 + node)*SEQ;
            int4   ia = *reinterpret_cast<const int4*>(indices + base);
            int4   ib = *reinterpret_cast<const int4*>(indices + base + 4);
            int4   ic = *reinterpret_cast<const int4*>(indices + base + 8);
            float4 wa = *reinterpret_cast<const float4*>(weight + base);
            float4 wb = *reinterpret_cast<const float4*>(weight + base + 4);
            float4 wc = *reinterpret_cast<const float4*>(weight + base + 8);
            ull a0 = 0, a1 = 0;
            #define GACC(II, WW) { \
                const float* src = xb + (size_t)(uint32)(II)*CH + lane*4; \
                ull p0, p1; ldg_cg_v4(src, p0, p1); \
                ull W = dup2(WW); \
                a0 = fma2(W, p0, a0); a1 = fma2(W, p1, a1); }
            GACC(ia.x, wa.x) GACC(ia.y, wa.y) GACC(ia.z, wa.z) GACC(ia.w, wa.w)
            GACC(ib.x, wb.x) GACC(ib.y, wb.y) GACC(ib.z, wb.z) GACC(ib.w, wb.w)
            GACC(ic.x, wc.x) GACC(ic.y, wc.y) GACC(ic.z, wc.z) GACC(ic.w, wc.w)
            #undef GACC
            ulonglong2 gp = *reinterpret_cast<const ulonglong2*>(gate_s + node*GP + lane*4);
            ull o0 = mul2(a0, add2(gp.x, bias0));
            ull o1 = mul2(a1, add2(gp.y, bias1));
            float* op = out + ((size_t)b*N_NODES + (size_t)(v0 + node))*CH + lane*4;
            asm volatile("st.global.cs.v2.b64 [%0], {%1,%2};" :: "l"(op), "l"(o0), "l"(o1) : "memory");
        }

        __syncthreads();   // gather done reading gate

        // ---- Stage next tile (overwrites A/gate smem) ----
        const int nxt = t + gridDim.x;
        if (nxt < total_tiles) stage(nxt);
    }
}

extern "C" void kernel_launch(void* const* d_in, const int* in_sizes, int n_in,
                              void* d_out, int out_size)
{
    (void)in_sizes; (void)n_in; (void)out_size;
    const float* x       = (const float*)d_in[0];
    const int*   indices = (const int*)  d_in[1];
    const float* weight  = (const float*)d_in[2];
    const float* gate_w  = (const float*)d_in[3];
    const float* gate_b  = (const float*)d_in[4];
    float*       out     = (float*)d_out;

    build_wfrag_kernel<<<4, 256>>>(gate_w);

    cudaFuncSetAttribute(gated_spiral_kernel,
                         cudaFuncAttributeMaxDynamicSharedMemorySize, SM_TOTAL);

    int sm_count = 148;
    cudaDeviceGetAttribute(&sm_count, cudaDevAttrMultiProcessorCount, 0);

    gated_spiral_kernel<<<3*sm_count, NTHREADS, SM_TOTAL>>>(
        x, indices, weight, gate_b, out);
}